// round 2
// baseline (speedup 1.0000x reference)
#include <cuda_runtime.h>
#include <math.h>
#include <stdint.h>

#define NBOX 2000
#define NC 21
#define MAXPC 50
#define MAXPI 100
#define NEGV (-1000000000.0f)
#define SORTN 2048
#define SBOX 512          // sorted boxes cached in smem (scan rarely goes past ~64)

// ---------------- device scratch (no allocations allowed) ----------------
__device__ float g_boxes[NBOX * 4];
__device__ float g_area[NBOX];
__device__ int   g_order[NC * NBOX];
__device__ float g_mscore[NC * NBOX];

// ---------------- 1) decode boxes ----------------
__global__ void k_decode(const float* __restrict__ props,
                         const float* __restrict__ deltas) {
    int i = blockIdx.x * blockDim.x + threadIdx.x;
    if (i >= NBOX) return;
    float y1 = props[i * 4 + 0], x1 = props[i * 4 + 1];
    float y2 = props[i * 4 + 2], x2 = props[i * 4 + 3];
    float h = __fsub_rn(y2, y1);
    float w = __fsub_rn(x2, x1);
    // explicit rn ops: no fma contraction, match reference op-for-op
    float cy = __fadd_rn(y1, __fmul_rn(0.5f, h));
    float cx = __fadd_rn(x1, __fmul_rn(0.5f, w));
    float dy = deltas[i * 4 + 0], dx = deltas[i * 4 + 1];
    float dh = deltas[i * 4 + 2], dw = deltas[i * 4 + 3];
    float pcy = __fadd_rn(__fmul_rn(dy, h), cy);
    float pcx = __fadd_rn(__fmul_rn(dx, w), cx);
    float ph = __fmul_rn(h, expf(dh));
    float pw = __fmul_rn(w, expf(dw));
    float by1 = __fsub_rn(pcy, __fmul_rn(0.5f, ph));
    float bx1 = __fsub_rn(pcx, __fmul_rn(0.5f, pw));
    float by2 = __fadd_rn(pcy, __fmul_rn(0.5f, ph));
    float bx2 = __fadd_rn(pcx, __fmul_rn(0.5f, pw));
    g_boxes[i * 4 + 0] = by1;
    g_boxes[i * 4 + 1] = bx1;
    g_boxes[i * 4 + 2] = by2;
    g_boxes[i * 4 + 3] = bx2;
    g_area[i] = __fmul_rn(__fsub_rn(by2, by1), __fsub_rn(bx2, bx1));
}

// comparator: "a before b" == (score desc, idx asc) — stable argsort of -score
__device__ __forceinline__ bool better(float sa, int ia, float sb, int ib) {
    return (sa > sb) || (sa == sb && ia < ib);
}

// IoU with exact reference op ordering
__device__ __forceinline__ float iou_ref(float ay1, float ax1, float ay2, float ax2, float aar,
                                         float by1, float bx1, float by2, float bx2, float bar) {
    float iy1 = fmaxf(ay1, by1);
    float ix1 = fmaxf(ax1, bx1);
    float iy2 = fminf(ay2, by2);
    float ix2 = fminf(ax2, bx2);
    float inter = __fmul_rn(fmaxf(__fsub_rn(iy2, iy1), 0.0f),
                            fmaxf(__fsub_rn(ix2, ix1), 0.0f));
    float uni = __fsub_rn(__fadd_rn(aar, bar), inter);
    return __fdiv_rn(inter, fmaxf(uni, 1e-8f));
}

// ---------------- 2) fused per-class: sort + greedy NMS + masked scores ----------------
__global__ void __launch_bounds__(1024, 1) k_class(const float* __restrict__ score) {
    int c = blockIdx.x;
    __shared__ float ks[SORTN];
    __shared__ int   vi[SORTN];
    __shared__ float sy1[SBOX], sx1[SBOX], sy2[SBOX], sx2[SBOX], sar[SBOX];
    int tid = threadIdx.x;

    // load scores for class c (stable keys)
    for (int i = tid; i < SORTN; i += 1024) {
        if (i < NBOX) { ks[i] = score[i * NC + c]; vi[i] = i; }
        else          { ks[i] = __int_as_float(0xff800000); vi[i] = 0x7fffffff; }
    }
    __syncthreads();

    // bitonic sort, "better" first
    for (int k = 2; k <= SORTN; k <<= 1) {
        for (int j = k >> 1; j > 0; j >>= 1) {
            for (int i = tid; i < SORTN; i += 1024) {
                int ixj = i ^ j;
                if (ixj > i) {
                    float a = ks[i], b = ks[ixj];
                    int ai = vi[i], bi = vi[ixj];
                    bool up = ((i & k) == 0);
                    bool sw = up ? better(b, bi, a, ai) : better(a, ai, b, bi);
                    if (sw) { ks[i] = b; ks[ixj] = a; vi[i] = bi; vi[ixj] = ai; }
                }
            }
            __syncthreads();
        }
    }

    // emit order, init masked scores to NEG, gather top-SBOX sorted boxes to smem
    for (int i = tid; i < SORTN; i += 1024) {
        if (i < NBOX) {
            g_order[c * NBOX + i]  = vi[i];
            g_mscore[c * NBOX + i] = NEGV;
        }
        if (i < SBOX) {
            int o = vi[i];
            sy1[i] = g_boxes[o * 4 + 0];
            sx1[i] = g_boxes[o * 4 + 1];
            sy2[i] = g_boxes[o * 4 + 2];
            sx2[i] = g_boxes[o * 4 + 3];
            sar[i] = g_area[o];
        }
    }
    __syncthreads();

    // warp 0: sequential greedy NMS against kept list (<= MAXPC entries).
    // Kept slots live in lane registers: lane l owns slots l and l+32.
    if (tid < 32) {
        int lane = tid;
        // sentinel: y1=2e9 guarantees inter==0, area=0 -> iou = 0
        float ky1a = 2e9f, kx1a = 2e9f, ky2a = 2e9f, kx2a = 2e9f, kara = 0.0f;
        float ky1b = 2e9f, kx1b = 2e9f, ky2b = 2e9f, kx2b = 2e9f, karb = 0.0f;
        int kc = 0;
        for (int i = 0; i < NBOX; i++) {
            float cy1, cx1, cy2, cx2, car;
            if (i < SBOX) {
                cy1 = sy1[i]; cx1 = sx1[i]; cy2 = sy2[i]; cx2 = sx2[i]; car = sar[i];
            } else {                       // rare: scan past cached prefix
                int o = vi[i];
                cy1 = g_boxes[o * 4 + 0]; cx1 = g_boxes[o * 4 + 1];
                cy2 = g_boxes[o * 4 + 2]; cx2 = g_boxes[o * 4 + 3];
                car = g_area[o];
            }
            float i1 = iou_ref(cy1, cx1, cy2, cx2, car, ky1a, kx1a, ky2a, kx2a, kara);
            float i2 = iou_ref(cy1, cx1, cy2, cx2, car, ky1b, kx1b, ky2b, kx2b, karb);
            bool sup = (i1 > 0.7f) || (i2 > 0.7f);
            unsigned b = __ballot_sync(0xffffffffu, sup);
            if (b == 0u) {                 // kept (uniform decision)
                if (lane == (kc & 31)) {
                    if (kc < 32) { ky1a = cy1; kx1a = cx1; ky2a = cy2; kx2a = cx2; kara = car; }
                    else         { ky1b = cy1; kx1b = cx1; ky2b = cy2; kx2b = cx2; karb = car; }
                }
                kc++;
                if (lane == 0) g_mscore[c * NBOX + i] = ks[i];
                if (kc == MAXPC) break;    // later rows are invalid either way
            }
        }
    }
}

// ---------------- 3) global top-100 ----------------
__global__ void k_topk(float* __restrict__ out) {
    __shared__ float cs[SORTN];
    __shared__ int   ci[SORTN];
    __shared__ int   cnt;
    int tid = threadIdx.x;
    if (tid == 0) cnt = 0;
    for (int i = tid; i < SORTN; i += blockDim.x) {
        cs[i] = __int_as_float(0xff800000);
        ci[i] = 0x7fffffff;
    }
    __syncthreads();
    // compact valid entries; at most 21*50 = 1050
    for (int f = tid; f < NC * NBOX; f += blockDim.x) {
        float s = g_mscore[f];
        if (s > -1e8f) {
            int p = atomicAdd(&cnt, 1);
            if (p < SORTN) { cs[p] = s; ci[p] = f; }
        }
    }
    __syncthreads();
    int V = cnt;
    // bitonic sort desc by (score desc, flat idx asc) — matches lax.top_k ties
    for (int k = 2; k <= SORTN; k <<= 1) {
        for (int j = k >> 1; j > 0; j >>= 1) {
            for (int i = tid; i < SORTN; i += blockDim.x) {
                int ixj = i ^ j;
                if (ixj > i) {
                    float a = cs[i], b = cs[ixj];
                    int ai = ci[i], bi = ci[ixj];
                    bool up = ((i & k) == 0);
                    bool sw = up ? better(b, bi, a, ai) : better(a, ai, b, bi);
                    if (sw) { cs[i] = b; cs[ixj] = a; ci[i] = bi; ci[ixj] = ai; }
                }
            }
            __syncthreads();
        }
    }
    // emit boxes + class ids
    if (tid < MAXPI && tid < V) {
        int f = ci[tid];
        int o = g_order[f];
        out[tid * 4 + 0] = g_boxes[o * 4 + 0];
        out[tid * 4 + 1] = g_boxes[o * 4 + 1];
        out[tid * 4 + 2] = g_boxes[o * 4 + 2];
        out[tid * 4 + 3] = g_boxes[o * 4 + 3];
        out[4 * MAXPI + tid] = (float)(f / NBOX);
    }
    // rare fallback: fewer than 100 valid -> NEG entries by lowest flat index
    if (tid == 0 && V < MAXPI) {
        int r = V;
        for (int f = 0; f < NC * NBOX && r < MAXPI; f++) {
            if (g_mscore[f] <= -1e8f) {
                int o = g_order[f];
                out[r * 4 + 0] = g_boxes[o * 4 + 0];
                out[r * 4 + 1] = g_boxes[o * 4 + 1];
                out[r * 4 + 2] = g_boxes[o * 4 + 2];
                out[r * 4 + 3] = g_boxes[o * 4 + 3];
                out[4 * MAXPI + r] = (float)(f / NBOX);
                r++;
            }
        }
    }
}

// ---------------- launch ----------------
extern "C" void kernel_launch(void* const* d_in, const int* in_sizes, int n_in,
                              void* d_out, int out_size) {
    const float* props  = (const float*)d_in[0];   // rpn_proposals_bboxes (2000,4)
    const float* deltas = (const float*)d_in[1];   // roi_bboxes_txtytwth  (2000,4)
    const float* score  = (const float*)d_in[2];   // roi_score            (2000,21)
    float* out = (float*)d_out;                    // 100*4 boxes ++ 100 cls

    k_decode<<<(NBOX + 255) / 256, 256>>>(props, deltas);
    k_class<<<NC, 1024>>>(score);
    k_topk<<<1, 1024>>>(out);
}

// round 5
// speedup vs baseline: 1.4217x; 1.4217x over previous
#include <cuda_runtime.h>
#include <math.h>
#include <stdint.h>

#define NBOX 2000
#define NC 21
#define MAXPC 50
#define MAXPI 100
#define SORTN 2048

// ---------------- device scratch (no allocations allowed) ----------------
__device__ unsigned long long g_kkey[NC * MAXPC];  // packed (score,idx) of kept entries; 0 = empty
__device__ int                g_ko[NC * MAXPC];    // original box idx of kept entries
__device__ int                g_kcnt[NC];
__device__ int                g_order[NC * NBOX];  // full sorted order (fallback path only)
__device__ int                g_done = 0;          // last-block ticket (self-resetting)

// orderable-float packing: larger u64 == better (score desc, idx asc)
__device__ __forceinline__ unsigned ord_f(float s) {
    unsigned u = __float_as_uint(s);
    return (u & 0x80000000u) ? ~u : (u | 0x80000000u);
}
__device__ __forceinline__ unsigned long long pack_key(float s, unsigned idx) {
    return ((unsigned long long)ord_f(s) << 32) | (unsigned long long)(0xFFFFFFFFu - idx);
}
__device__ __forceinline__ unsigned key_idx(unsigned long long k) {
    return 0xFFFFFFFFu - (unsigned)(k & 0xFFFFFFFFu);
}

// decode with exact reference op ordering (no fma contraction)
__device__ __forceinline__ float4 decode_box(const float* __restrict__ props,
                                             const float* __restrict__ deltas, int i) {
    float y1 = props[i * 4 + 0], x1 = props[i * 4 + 1];
    float y2 = props[i * 4 + 2], x2 = props[i * 4 + 3];
    float h = __fsub_rn(y2, y1);
    float w = __fsub_rn(x2, x1);
    float cy = __fadd_rn(y1, __fmul_rn(0.5f, h));
    float cx = __fadd_rn(x1, __fmul_rn(0.5f, w));
    float dy = deltas[i * 4 + 0], dx = deltas[i * 4 + 1];
    float dh = deltas[i * 4 + 2], dw = deltas[i * 4 + 3];
    float pcy = __fadd_rn(__fmul_rn(dy, h), cy);
    float pcx = __fadd_rn(__fmul_rn(dx, w), cx);
    float ph = __fmul_rn(h, expf(dh));
    float pw = __fmul_rn(w, expf(dw));
    float4 b;
    b.x = __fsub_rn(pcy, __fmul_rn(0.5f, ph));   // y1
    b.y = __fsub_rn(pcx, __fmul_rn(0.5f, pw));   // x1
    b.z = __fadd_rn(pcy, __fmul_rn(0.5f, ph));   // y2
    b.w = __fadd_rn(pcx, __fmul_rn(0.5f, pw));   // x2
    return b;
}

__device__ __forceinline__ float area_of(float4 b) {
    return __fmul_rn(__fsub_rn(b.z, b.x), __fsub_rn(b.w, b.y));
}

// IoU with exact reference op ordering
__device__ __forceinline__ float iou_ref(float4 a, float aar, float4 b, float bar) {
    float iy1 = fmaxf(a.x, b.x);
    float ix1 = fmaxf(a.y, b.y);
    float iy2 = fminf(a.z, b.z);
    float ix2 = fminf(a.w, b.w);
    float inter = __fmul_rn(fmaxf(__fsub_rn(iy2, iy1), 0.0f),
                            fmaxf(__fsub_rn(ix2, ix1), 0.0f));
    float uni = __fsub_rn(__fadd_rn(aar, bar), inter);
    return __fdiv_rn(inter, fmaxf(uni, 1e-8f));
}

__device__ __forceinline__ unsigned long long cmpsel(unsigned long long a,
                                                     unsigned long long b, bool takeMax) {
    unsigned long long mx = (a > b) ? a : b;
    unsigned long long mn = (a > b) ? b : a;
    return takeMax ? mx : mn;
}

// in-register bitonic phases: the j==32 step (in-thread) plus j=16..1 (shfl).
// i0 = position of r0 (lower), i1 = i0 + 32.
__device__ __forceinline__ void reg_phases(unsigned long long& r0, unsigned long long& r1,
                                           int i0, int i1, int k, int jstart) {
    if (jstart >= 32) {
        bool up = ((i0 & k) == 0);               // same bit for i1 (k >= 64 here)
        unsigned long long mx = (r0 > r1) ? r0 : r1;
        unsigned long long mn = (r0 > r1) ? r1 : r0;
        r0 = up ? mx : mn;
        r1 = up ? mn : mx;
    }
    int j0 = (jstart >= 32) ? 16 : jstart;
    #pragma unroll
    for (int j = 16; j >= 1; j >>= 1) {
        if (j > j0) continue;
        unsigned long long o0 = __shfl_xor_sync(0xffffffffu, r0, j);
        unsigned long long o1 = __shfl_xor_sync(0xffffffffu, r1, j);
        bool up0 = ((i0 & k) == 0);
        bool up1 = ((i1 & k) == 0);
        r0 = cmpsel(r0, o0, ((i0 & j) == 0) == up0);
        r1 = cmpsel(r1, o1, ((i1 & j) == 0) == up1);
    }
}

// ---------------- fused: per-class decode + sort + greedy NMS, then last block does top-100 ----------------
__global__ void __launch_bounds__(1024, 1) k_all(const float* __restrict__ props,
                                                 const float* __restrict__ deltas,
                                                 const float* __restrict__ score,
                                                 float* __restrict__ out) {
    int c = blockIdx.x;
    __shared__ unsigned long long kk[SORTN];     // 16384 B (reused by top-k phase)
    __shared__ float4 sbox[NBOX];                // 32000 B  (total 48384 <= 48KB)
    __shared__ int s_last;
    int tid = threadIdx.x;
    int w = tid >> 5, l = tid & 31;
    int i0 = w * 64 + l, i1 = i0 + 32;

    // decode all boxes into smem (by original index)
    for (int i = tid; i < NBOX; i += 1024)
        sbox[i] = decode_box(props, deltas, i);

    // keys straight into registers (elements i0, i1 of the sort array)
    unsigned long long r0 = (i0 < NBOX) ? pack_key(score[i0 * NC + c], (unsigned)i0) : 0ULL;
    unsigned long long r1 = (i1 < NBOX) ? pack_key(score[i1 * NC + c], (unsigned)i1) : 0ULL;

    // stages k=2..64: entirely in registers, no barriers
    #pragma unroll
    for (int k = 2; k <= 64; k <<= 1)
        reg_phases(r0, r1, i0, i1, k, k >> 1);

    // stages k=128..2048: strides >=64 via smem, strides <=32 in registers
    #pragma unroll
    for (int k = 128; k <= SORTN; k <<= 1) {
        kk[i0] = r0; kk[i1] = r1;
        __syncthreads();
        for (int j = k >> 1; j >= 64; j >>= 1) {
            #pragma unroll
            for (int t = tid; t < SORTN; t += 1024) {
                int x = t ^ j;
                if (x > t) {
                    unsigned long long a = kk[t], b = kk[x];
                    bool up = ((t & k) == 0);
                    bool sw = up ? (b > a) : (b < a);
                    if (sw) { kk[t] = b; kk[x] = a; }
                }
            }
            __syncthreads();
        }
        r0 = kk[i0]; r1 = kk[i1];
        reg_phases(r0, r1, i0, i1, k, 32);
    }
    kk[i0] = r0; kk[i1] = r1;
    __syncthreads();

    if (w == 0) {
        // warp 0: sequential greedy NMS; kept boxes in lane registers (2 slots/lane)
        float4 ka = make_float4(2e9f, 2e9f, 2e9f, 2e9f);   // sentinel: inter==0, area==0
        float4 kb = ka;
        float kaar = 0.0f, kbar = 0.0f;
        int kc = 0;
        for (int i = 0; i < NBOX; i++) {
            unsigned long long key = kk[i];                // broadcast LDS
            int o = (int)key_idx(key);
            float4 cb = sbox[o];
            float car = area_of(cb);
            bool sup = (iou_ref(cb, car, ka, kaar) > 0.7f) ||
                       (iou_ref(cb, car, kb, kbar) > 0.7f);
            unsigned bal = __ballot_sync(0xffffffffu, sup);
            if (bal == 0u) {                               // kept (uniform decision)
                if (l == (kc & 31)) {
                    if (kc < 32) { ka = cb; kaar = car; }
                    else         { kb = cb; kbar = car; }
                }
                if (l == 0) {
                    g_kkey[c * MAXPC + kc] = key;
                    g_ko[c * MAXPC + kc] = o;
                }
                kc++;
                if (kc == MAXPC) break;                    // later rows invalid either way
            }
        }
        // zero-fill unused kept slots; publish count
        for (int j = kc + l; j < MAXPC; j += 32)
            g_kkey[c * MAXPC + j] = 0ULL;
        if (l == 0) g_kcnt[c] = kc;
    } else {
        // warps 1..31: emit full sorted order (needed only by rare fallback path)
        for (int i = tid - 32; i < NBOX; i += 992)
            g_order[c * NBOX + i] = (int)key_idx(kk[i]);
    }

    // ---- ticket: last finished block performs global top-100 ----
    __threadfence();
    __syncthreads();
    if (tid == 0)
        s_last = (atomicAdd(&g_done, 1) == NC - 1) ? 1 : 0;
    __syncthreads();
    if (!s_last) return;

    if (tid == 0) atomicExch(&g_done, 0);                  // reset for next graph replay

    // load all 1050 kept keys into smem (reuse kk region; bypass L1 for cross-SM data)
    unsigned long long* sk = kk;
    for (int t = tid; t < NC * MAXPC; t += 1024)
        sk[t] = __ldcg(&g_kkey[t]);
    __syncthreads();

    // rank by counting strictly-better keys (keys are unique -> ranks 0..V-1 distinct)
    for (int e = tid; e < NC * MAXPC; e += 1024) {
        unsigned long long my = sk[e];
        if (my == 0ULL) continue;
        int cnt = 0;
        for (int j = 0; j < NC * MAXPC; j++)
            cnt += (sk[j] > my) ? 1 : 0;
        if (cnt < MAXPI) {
            int o = __ldcg(&g_ko[e]);
            float4 b = decode_box(props, deltas, o);
            out[cnt * 4 + 0] = b.x;
            out[cnt * 4 + 1] = b.y;
            out[cnt * 4 + 2] = b.z;
            out[cnt * 4 + 3] = b.w;
            out[4 * MAXPI + cnt] = (float)(e / MAXPC);
        }
    }

    // rare fallback: fewer than 100 kept total -> fill with NEG entries (lowest flat idx first)
    if (tid == 0) {
        int V = 0;
        for (int cc = 0; cc < NC; cc++) V += __ldcg(&g_kcnt[cc]);
        if (V < MAXPI) {
            int r = V;
            for (int cc = 0; cc < NC && r < MAXPI; cc++) {
                int pj = 0, kcnt = __ldcg(&g_kcnt[cc]);
                for (int i = 0; i < NBOX && r < MAXPI; i++) {
                    int o_here = __ldcg(&g_order[cc * NBOX + i]);
                    if (pj < kcnt && o_here == __ldcg(&g_ko[cc * MAXPC + pj])) { pj++; continue; }
                    float4 b = decode_box(props, deltas, o_here);
                    out[r * 4 + 0] = b.x;
                    out[r * 4 + 1] = b.y;
                    out[r * 4 + 2] = b.z;
                    out[r * 4 + 3] = b.w;
                    out[4 * MAXPI + r] = (float)cc;
                    r++;
                }
            }
        }
    }
}

// ---------------- launch ----------------
extern "C" void kernel_launch(void* const* d_in, const int* in_sizes, int n_in,
                              void* d_out, int out_size) {
    const float* props  = (const float*)d_in[0];   // rpn_proposals_bboxes (2000,4)
    const float* deltas = (const float*)d_in[1];   // roi_bboxes_txtytwth  (2000,4)
    const float* score  = (const float*)d_in[2];   // roi_score            (2000,21)
    float* out = (float*)d_out;                    // 100*4 boxes ++ 100 cls

    k_all<<<NC, 1024>>>(props, deltas, score, out);
}

// round 15
// speedup vs baseline: 1.5143x; 1.0651x over previous
#include <cuda_runtime.h>
#include <math.h>
#include <stdint.h>

#define NBOX 2000
#define NC 21
#define MAXPC 50
#define MAXPI 100
#define CANDN 512            // sorted candidate slots (power of 2)
#define CMIN 320             // min candidates selected

// ---------------- device scratch (no allocations allowed) ----------------
__device__ unsigned long long g_kkey[NC * MAXPC];  // packed (score,idx) kept; 0 = empty
__device__ int                g_ko[NC * MAXPC];    // original box idx of kept entries
__device__ int                g_kcnt[NC];
__device__ int                g_done = 0;          // last-block ticket (self-resetting)

// orderable-float packing: larger u64 == better (score desc, idx asc)
__device__ __forceinline__ unsigned ord_f(float s) {
    unsigned u = __float_as_uint(s);
    return (u & 0x80000000u) ? ~u : (u | 0x80000000u);
}
__device__ __forceinline__ unsigned long long pack_key(float s, unsigned idx) {
    return ((unsigned long long)ord_f(s) << 32) | (unsigned long long)(0xFFFFFFFFu - idx);
}
__device__ __forceinline__ unsigned key_idx(unsigned long long k) {
    return 0xFFFFFFFFu - (unsigned)(k & 0xFFFFFFFFu);
}

// decode with exact reference op ordering (no fma contraction)
__device__ __forceinline__ float4 decode_box(const float* __restrict__ props,
                                             const float* __restrict__ deltas, int i) {
    float y1 = props[i * 4 + 0], x1 = props[i * 4 + 1];
    float y2 = props[i * 4 + 2], x2 = props[i * 4 + 3];
    float h = __fsub_rn(y2, y1);
    float w = __fsub_rn(x2, x1);
    float cy = __fadd_rn(y1, __fmul_rn(0.5f, h));
    float cx = __fadd_rn(x1, __fmul_rn(0.5f, w));
    float dy = deltas[i * 4 + 0], dx = deltas[i * 4 + 1];
    float dh = deltas[i * 4 + 2], dw = deltas[i * 4 + 3];
    float pcy = __fadd_rn(__fmul_rn(dy, h), cy);
    float pcx = __fadd_rn(__fmul_rn(dx, w), cx);
    float ph = __fmul_rn(h, expf(dh));
    float pw = __fmul_rn(w, expf(dw));
    float4 b;
    b.x = __fsub_rn(pcy, __fmul_rn(0.5f, ph));
    b.y = __fsub_rn(pcx, __fmul_rn(0.5f, pw));
    b.z = __fadd_rn(pcy, __fmul_rn(0.5f, ph));
    b.w = __fadd_rn(pcx, __fmul_rn(0.5f, pw));
    return b;
}

__device__ __forceinline__ float area_of(float4 b) {
    return __fmul_rn(__fsub_rn(b.z, b.x), __fsub_rn(b.w, b.y));
}

// IoU with exact reference op ordering
__device__ __forceinline__ float iou_ref(float4 a, float aar, float4 b, float bar) {
    float iy1 = fmaxf(a.x, b.x);
    float ix1 = fmaxf(a.y, b.y);
    float iy2 = fminf(a.z, b.z);
    float ix2 = fminf(a.w, b.w);
    float inter = __fmul_rn(fmaxf(__fsub_rn(iy2, iy1), 0.0f),
                            fmaxf(__fsub_rn(ix2, ix1), 0.0f));
    float uni = __fsub_rn(__fadd_rn(aar, bar), inter);
    return __fdiv_rn(inter, fmaxf(uni, 1e-8f));
}

__device__ __forceinline__ unsigned long long cmpsel(unsigned long long a,
                                                     unsigned long long b, bool takeMax) {
    unsigned long long mx = (a > b) ? a : b;
    unsigned long long mn = (a > b) ? b : a;
    return takeMax ? mx : mn;
}

// in-register bitonic phases: optional in-thread j==32 step plus j=16..1 shfl steps.
__device__ __forceinline__ void reg_phases(unsigned long long& r0, unsigned long long& r1,
                                           int i0, int i1, int k, int jstart) {
    if (jstart >= 32) {
        bool up = ((i0 & k) == 0);
        unsigned long long mx = (r0 > r1) ? r0 : r1;
        unsigned long long mn = (r0 > r1) ? r1 : r0;
        r0 = up ? mx : mn;
        r1 = up ? mn : mx;
    }
    int j0 = (jstart >= 32) ? 16 : jstart;
    #pragma unroll
    for (int j = 16; j >= 1; j >>= 1) {
        if (j > j0) continue;
        unsigned long long o0 = __shfl_xor_sync(0xffffffffu, r0, j);
        unsigned long long o1 = __shfl_xor_sync(0xffffffffu, r1, j);
        bool up0 = ((i0 & k) == 0);
        bool up1 = ((i1 & k) == 0);
        r0 = cmpsel(r0, o0, ((i0 & j) == 0) == up0);
        r1 = cmpsel(r1, o1, ((i1 & j) == 0) == up1);
    }
}

// ---------------- fused everything ----------------
__global__ void __launch_bounds__(1024, 1) k_all(const float* __restrict__ props,
                                                 const float* __restrict__ deltas,
                                                 const float* __restrict__ score,
                                                 float* __restrict__ out) {
    int c = blockIdx.x;
    __shared__ unsigned long long kk[NC * MAXPC];   // >= CANDN; sort area + topk keys (8400 B)
    __shared__ float4 sbox[CANDN];                  // candidate boxes (8192 B)
    __shared__ int hist[256];
    __shared__ unsigned long long red[32];
    __shared__ unsigned long long s_lastkey;
    __shared__ int s_kc, s_done2, s_B, s_Vc, s_cnt, s_last;
    int tid = threadIdx.x;
    int w = tid >> 5, l = tid & 31;

    if (tid < 256) hist[tid] = 0;
    for (int t = tid; t < CANDN; t += 1024) kk[t] = 0ULL;
    if (tid == 0) { s_cnt = 0; s_done2 = 0; }
    __syncthreads();

    // ---- histogram over score buckets (monotone in score) ----
    for (int i = tid; i < NBOX; i += 1024) {
        float s = score[i * NC + c];
        int b = (int)(__fmul_rn(s, 256.0f));
        b = b < 0 ? 0 : (b > 255 ? 255 : b);
        atomicAdd(&hist[b], 1);
    }
    __syncthreads();

    // ---- warp 0: suffix counts; B = largest bucket with suffix >= CMIN ----
    if (w == 0) {
        int loc[8], lsum = 0;
        #pragma unroll
        for (int q = 0; q < 8; q++) { loc[q] = hist[l * 8 + q]; lsum += loc[q]; }
        int v = lsum;                                   // sum over lanes >= l
        #pragma unroll
        for (int off = 1; off < 32; off <<= 1) {
            int o = __shfl_down_sync(0xffffffffu, v, off);
            if (l + off < 32) v += o;
        }
        int base = v - lsum;
        int best = -1, bestS = 0, run = base;
        #pragma unroll
        for (int q = 7; q >= 0; q--) {
            run += loc[q];
            if (run >= CMIN && (l * 8 + q) > best) { best = l * 8 + q; bestS = run; }
        }
        int pk = (best << 16) | bestS;                  // best=-1 -> negative, loses max
        #pragma unroll
        for (int off = 16; off >= 1; off >>= 1) {
            int o = __shfl_xor_sync(0xffffffffu, pk, off);
            pk = o > pk ? o : pk;
        }
        if (l == 0) { s_B = pk >> 16; s_Vc = pk & 0xFFFF; }
    }
    __syncthreads();
    int B = s_B, Vc = s_Vc;
    bool ok = (Vc <= CANDN);                            // pathological fat bucket -> slow path

    // kept-list registers (warp 0; persist across phases). Sentinel: inter==0, area==0.
    float4 ka = make_float4(2e9f, 2e9f, 2e9f, 2e9f), kb = ka;
    float kaar = 0.0f, kbar = 0.0f;

    if (ok) {
        // ---- compact candidates (unordered; sort makes it deterministic) ----
        for (int i = tid; i < NBOX; i += 1024) {
            float s = score[i * NC + c];
            int b = (int)(__fmul_rn(s, 256.0f));
            b = b < 0 ? 0 : (b > 255 ? 255 : b);
            if (b >= B) {
                int p = atomicAdd(&s_cnt, 1);
                kk[p] = pack_key(s, (unsigned)i);
            }
        }
        __syncthreads();

        // ---- bitonic sort 512 (threads 0..255 hold 2 keys each) ----
        int i0 = w * 64 + l, i1 = i0 + 32;              // valid for w < 8
        unsigned long long r0 = 0, r1 = 0;
        if (w < 8) {
            r0 = kk[i0]; r1 = kk[i1];
            #pragma unroll
            for (int k = 2; k <= 64; k <<= 1)
                reg_phases(r0, r1, i0, i1, k, k >> 1);
        }
        #pragma unroll
        for (int k = 128; k <= CANDN; k <<= 1) {
            if (w < 8) { kk[i0] = r0; kk[i1] = r1; }
            __syncthreads();
            for (int j = k >> 1; j >= 64; j >>= 1) {
                if (tid < 256) {
                    #pragma unroll
                    for (int t = tid; t < CANDN; t += 256) {
                        int x = t ^ j;
                        if (x > t) {
                            unsigned long long a = kk[t], bb2 = kk[x];
                            bool up = ((t & k) == 0);
                            bool sw = up ? (bb2 > a) : (bb2 < a);
                            if (sw) { kk[t] = bb2; kk[x] = a; }
                        }
                    }
                }
                __syncthreads();
            }
            if (w < 8) { r0 = kk[i0]; r1 = kk[i1]; reg_phases(r0, r1, i0, i1, k, 32); }
        }
        if (w < 8) { kk[i0] = r0; kk[i1] = r1; }
        __syncthreads();

        // ---- decode candidate boxes (positional) ----
        for (int t = tid; t < Vc; t += 1024)
            sbox[t] = decode_box(props, deltas, (int)key_idx(kk[t]));
        __syncthreads();

        // ---- warp 0: serial greedy NMS over sorted candidates ----
        if (w == 0) {
            int kc = 0;
            for (int i = 0; i < Vc; i++) {
                unsigned long long key = kk[i];
                float4 cb = sbox[i];
                float car = area_of(cb);
                bool sup = (iou_ref(cb, car, ka, kaar) > 0.7f) ||
                           (iou_ref(cb, car, kb, kbar) > 0.7f);
                unsigned bal = __ballot_sync(0xffffffffu, sup);
                if (bal == 0u) {
                    if (l == (kc & 31)) {
                        if (kc < 32) { ka = cb; kaar = car; }
                        else         { kb = cb; kbar = car; }
                    }
                    if (l == 0) {
                        g_kkey[c * MAXPC + kc] = key;
                        g_ko[c * MAXPC + kc] = (int)key_idx(key);
                    }
                    kc++;
                    if (kc == MAXPC) break;
                }
            }
            if (l == 0) { s_kc = kc; s_lastkey = kk[Vc - 1]; }
        }
    } else {
        if (tid == 0) { s_kc = 0; s_lastkey = ~0ULL; }  // slow path: select-as-you-go
    }
    __syncthreads();

    // ---- continuation (rare): iterative next-max NMS until 50 keeps or exhausted ----
    while (!s_done2 && s_kc < MAXPC) {
        unsigned long long lastk = s_lastkey;
        unsigned long long loc = 0;
        for (int i = tid; i < NBOX; i += 1024) {
            unsigned long long kkey = pack_key(score[i * NC + c], (unsigned)i);
            if (kkey < lastk && kkey > loc) loc = kkey;
        }
        #pragma unroll
        for (int off = 16; off >= 1; off >>= 1) {
            unsigned long long o = __shfl_xor_sync(0xffffffffu, loc, off);
            if (o > loc) loc = o;
        }
        if (l == 0) red[w] = loc;
        __syncthreads();
        if (w == 0) {
            unsigned long long best = red[l];
            #pragma unroll
            for (int off = 16; off >= 1; off >>= 1) {
                unsigned long long o = __shfl_xor_sync(0xffffffffu, best, off);
                if (o > best) best = o;
            }
            if (best == 0ULL) { if (l == 0) s_done2 = 1; }
            else {
                int o = (int)key_idx(best);
                float4 cb = decode_box(props, deltas, o);
                float car = area_of(cb);
                bool sup = (iou_ref(cb, car, ka, kaar) > 0.7f) ||
                           (iou_ref(cb, car, kb, kbar) > 0.7f);
                unsigned bal = __ballot_sync(0xffffffffu, sup);
                if (bal == 0u) {
                    int kc2 = s_kc;
                    if (l == (kc2 & 31)) {
                        if (kc2 < 32) { ka = cb; kaar = car; }
                        else          { kb = cb; kbar = car; }
                    }
                    if (l == 0) {
                        g_kkey[c * MAXPC + kc2] = best;
                        g_ko[c * MAXPC + kc2] = o;
                        s_kc = kc2 + 1;
                    }
                }
                if (l == 0) s_lastkey = best;
            }
        }
        __syncthreads();
    }

    // ---- publish kept count, zero-fill unused slots ----
    if (w == 0) {
        int kcf = s_kc;
        for (int j = kcf + l; j < MAXPC; j += 32)
            g_kkey[c * MAXPC + j] = 0ULL;
        if (l == 0) g_kcnt[c] = kcf;
    }

    // ---- ticket: last block performs global top-100 ----
    __threadfence();
    __syncthreads();
    if (tid == 0)
        s_last = (atomicAdd(&g_done, 1) == NC - 1) ? 1 : 0;
    __syncthreads();
    if (!s_last) return;
    if (tid == 0) atomicExch(&g_done, 0);               // reset for next graph replay

    for (int t = tid; t < NC * MAXPC; t += 1024)
        kk[t] = __ldcg(&g_kkey[t]);
    __syncthreads();

    // rank by counting strictly-better keys (keys unique -> distinct ranks)
    for (int e = tid; e < NC * MAXPC; e += 1024) {
        unsigned long long my = kk[e];
        if (my == 0ULL) continue;
        int cnt = 0;
        for (int j = 0; j < NC * MAXPC; j++)
            cnt += (kk[j] > my) ? 1 : 0;
        if (cnt < MAXPI) {
            int o = __ldcg(&g_ko[e]);
            float4 b = decode_box(props, deltas, o);
            out[cnt * 4 + 0] = b.x;
            out[cnt * 4 + 1] = b.y;
            out[cnt * 4 + 2] = b.z;
            out[cnt * 4 + 3] = b.w;
            out[4 * MAXPI + cnt] = (float)(e / MAXPC);
        }
    }
    __syncthreads();

    // rare fallback: fewer than 100 kept -> fill with NEG entries (ascending flat index:
    // class asc, sorted-position asc, skipping the valid kept entries). Warp 0 next-max.
    if (w == 0) {
        int V = 0;
        for (int cc = 0; cc < NC; cc++) V += __ldcg(&g_kcnt[cc]);
        if (V < MAXPI) {
            int r = V;
            for (int cc = 0; cc < NC && r < MAXPI; cc++) {
                unsigned long long lastk = ~0ULL;
                int kcnt = __ldcg(&g_kcnt[cc]);
                while (r < MAXPI) {
                    unsigned long long loc = 0;
                    for (int i = l; i < NBOX; i += 32) {
                        unsigned long long kkey = pack_key(score[i * NC + cc], (unsigned)i);
                        if (kkey < lastk && kkey > loc) loc = kkey;
                    }
                    #pragma unroll
                    for (int off = 16; off >= 1; off >>= 1) {
                        unsigned long long o = __shfl_xor_sync(0xffffffffu, loc, off);
                        if (o > loc) loc = o;
                    }
                    if (loc == 0ULL) break;             // class exhausted
                    int o = (int)key_idx(loc);
                    bool mine = false;
                    for (int q = l; q < kcnt; q += 32)
                        if (__ldcg(&g_ko[cc * MAXPC + q]) == o) mine = true;
                    unsigned bb = __ballot_sync(0xffffffffu, mine);
                    if (bb == 0u) {
                        if (l == 0) {
                            float4 b = decode_box(props, deltas, o);
                            out[r * 4 + 0] = b.x;
                            out[r * 4 + 1] = b.y;
                            out[r * 4 + 2] = b.z;
                            out[r * 4 + 3] = b.w;
                            out[4 * MAXPI + r] = (float)cc;
                        }
                        r++;
                    }
                    lastk = loc;
                }
            }
        }
    }
}

// ---------------- launch ----------------
extern "C" void kernel_launch(void* const* d_in, const int* in_sizes, int n_in,
                              void* d_out, int out_size) {
    const float* props  = (const float*)d_in[0];   // rpn_proposals_bboxes (2000,4)
    const float* deltas = (const float*)d_in[1];   // roi_bboxes_txtytwth  (2000,4)
    const float* score  = (const float*)d_in[2];   // roi_score            (2000,21)
    float* out = (float*)d_out;                    // 100*4 boxes ++ 100 cls

    k_all<<<NC, 1024>>>(props, deltas, score, out);
}